// round 14
// baseline (speedup 1.0000x reference)
#include <cuda_runtime.h>
#include <cuda_bf16.h>
#include <math.h>

#define TT 512
#define BB 128
#define EE 256
#define HH 512
#define G4 2048
#define VV 512

// ---------------- static device scratch ------------------------------------
__device__ float g_X[TT * BB * EE];
__device__ float g_pre0[TT * BB * G4];
__device__ float g_pre1[TT * BB * G4];
__device__ float g_cat[TT * BB * 2 * HH];
__device__ float g_hs0[TT * BB * HH];
__device__ float g_hs1[TT * BB * HH];
__device__ float g_fin[2][BB * 2 * HH];
__device__ float g_hinit[BB * HH];
__device__ float g_cinit[BB * HH];
__device__ unsigned g_barC[1];
__device__ unsigned g_wsp[6][2][32 * 256 * 64];
__device__ unsigned g_hsp[2][2][2][256 * 128];
__device__ float g_wx[7][2097152];

// ---------------- tf32 helpers ----------------------------------------------
__device__ __forceinline__ unsigned f2tf(float f) {
    unsigned r;
    asm("cvt.rna.tf32.f32 %0, %1;" : "=r"(r) : "f"(f));
    return r;
}
__device__ __forceinline__ float tfr(float f) { return __uint_as_float(f2tf(f)); }

// paired tf32 rounding: z selects set
__global__ void tfround2_kernel(const float* in0, float* out0, int n0,
                                const float* in1, float* out1, int n1) {
    const float* in = blockIdx.z ? in1 : in0;
    float* out = blockIdx.z ? out1 : out0;
    int n = blockIdx.z ? n1 : n0;
    int i = blockIdx.x * blockDim.x + threadIdx.x;
    if (i < n) out[i] = tfr(in[i]);
}

__global__ void tfround_kernel(const float* __restrict__ in, float* __restrict__ out, int n) {
    int i = blockIdx.x * blockDim.x + threadIdx.x;
    if (i < n) out[i] = tfr(in[i]);
}

// ---------------- small kernels --------------------------------------------
__global__ void embed_kernel(const int* __restrict__ x, const float* __restrict__ emb) {
    int p = blockIdx.x * blockDim.x + threadIdx.x;
    int e4 = p & (EE / 4 - 1);
    int tb = p >> 6;
    int b = tb & (BB - 1);
    int t = tb >> 7;
    int tok = x[b * TT + t];
    float4 v = reinterpret_cast<const float4*>(emb)[(size_t)tok * (EE / 4) + e4];
    v.x = tfr(v.x); v.y = tfr(v.y); v.z = tfr(v.z); v.w = tfr(v.w);
    reinterpret_cast<float4*>(g_X)[(size_t)tb * (EE / 4) + e4] = v;
}

// zero h-split buffers + barrier in one launch (grid 1024x256 covers 262144)
__global__ void initzero_kernel(float* hsp, unsigned* bar) {
    int i = blockIdx.x * blockDim.x + threadIdx.x;
    if (i == 0) bar[0] = 0u;
    if (i < 262144) hsp[i] = 0.f;
}

__global__ void initbar_kernel(unsigned* bar) { bar[0] = 0u; }

// ---------------- bf16 split helpers ----------------------------------------
__device__ __forceinline__ unsigned pack_bf16x2(float lo, float hi) {
    unsigned r;
    asm("cvt.rn.bf16x2.f32 %0, %1, %2;" : "=r"(r) : "f"(hi), "f"(lo));
    return r;
}

__device__ __forceinline__ void wconv_body(const float* W, unsigned* hi, unsigned* lo, int p) {
    int bn = p >> 14;
    int rem = p & 16383;
    int kp = rem >> 6;
    int c = rem & 63;
    int G = (c >> 4) * HH + bn * 16 + (c & 15);
    float w0 = W[(size_t)(2 * kp) * G4 + G];
    float w1 = W[(size_t)(2 * kp + 1) * G4 + G];
    __nv_bfloat16 b0 = __float2bfloat16_rn(w0);
    __nv_bfloat16 b1 = __float2bfloat16_rn(w1);
    hi[p] = (unsigned)__bfloat16_as_ushort(b0) |
            ((unsigned)__bfloat16_as_ushort(b1) << 16);
    lo[p] = pack_bf16x2(w0 - __bfloat162float(b0), w1 - __bfloat162float(b1));
}

// paired weight split: z selects set
__global__ void wconv2_kernel(const float* W0, unsigned* hi0, unsigned* lo0,
                              const float* W1, unsigned* hi1, unsigned* lo1) {
    int p = blockIdx.x * blockDim.x + threadIdx.x;   // 524288
    if (blockIdx.z) wconv_body(W1, hi1, lo1, p);
    else            wconv_body(W0, hi0, lo0, p);
}

__global__ void hsplit_kernel(const float* __restrict__ h,
                              unsigned* __restrict__ hi, unsigned* __restrict__ lo) {
    int p = blockIdx.x * blockDim.x + threadIdx.x;   // 32768
    int kp = p >> 7, m = p & 127;
    float v0 = h[(size_t)m * HH + 2 * kp];
    float v1 = h[(size_t)m * HH + 2 * kp + 1];
    __nv_bfloat16 b0 = __float2bfloat16_rn(v0);
    __nv_bfloat16 b1 = __float2bfloat16_rn(v1);
    hi[p] = (unsigned)__bfloat16_as_ushort(b0) |
            ((unsigned)__bfloat16_as_ushort(b1) << 16);
    lo[p] = pack_bf16x2(v0 - __bfloat162float(b0), v1 - __bfloat162float(b1));
}

// ---------------- cp.async + mma helpers -------------------------------------
__device__ __forceinline__ void cpasync16(void* smem, const void* gmem) {
    unsigned saddr = (unsigned)__cvta_generic_to_shared(smem);
    asm volatile("cp.async.cg.shared.global [%0], [%1], 16;\n" :: "r"(saddr), "l"(gmem));
}

__device__ __forceinline__ void mma_tf32(float* c, unsigned a0, unsigned a1,
                                         unsigned a2, unsigned a3,
                                         unsigned b0, unsigned b1) {
    asm volatile(
        "mma.sync.aligned.m16n8k8.row.col.f32.tf32.tf32.f32 "
        "{%0,%1,%2,%3}, {%4,%5,%6,%7}, {%8,%9}, {%0,%1,%2,%3};"
        : "+f"(c[0]), "+f"(c[1]), "+f"(c[2]), "+f"(c[3])
        : "r"(a0), "r"(a1), "r"(a2), "r"(a3), "r"(b0), "r"(b1));
}

// ---------------- tf32 GEMM, 3-stage cp.async, paired via blockIdx.z ---------
// A stage: [128][36]; W stage: [32][136]. 3 stages = 26880 floats = 107520 B.
__global__ __launch_bounds__(256) void tgemm_kernel(
    const float* __restrict__ A0, const float* __restrict__ W0,
    const float* __restrict__ bias0, float* __restrict__ C0,
    const float* __restrict__ A1, const float* __restrict__ W1,
    const float* __restrict__ bias1, float* __restrict__ C1,
    int M, int N, int K, int lda, int remap)
{
    extern __shared__ float ts[];
    const float* A = blockIdx.z ? A1 : A0;
    const float* W = blockIdx.z ? W1 : W0;
    const float* bias = blockIdx.z ? bias1 : bias0;
    float* C = blockIdx.z ? C1 : C0;

    float* Asm = ts;               // 3 x 4608
    float* Wsm = ts + 13824;       // 3 x 4352
    const int tid = threadIdx.x;
    const int m0 = blockIdx.y * 128, n0 = blockIdx.x * 128;
    const int warp = tid >> 5, lane = tid & 31;
    const int wm = (warp & 1) * 64;
    const int wn = (warp >> 1) * 32;
    const int gid = lane >> 2, tig = lane & 3;

    float acc[4][4][4];
#pragma unroll
    for (int mt = 0; mt < 4; mt++)
#pragma unroll
        for (int nt = 0; nt < 4; nt++)
#pragma unroll
            for (int u = 0; u < 4; u++) acc[mt][nt][u] = 0.f;

    auto load_chunk = [&](int st, int k0) {
        float* Ad = Asm + st * 4608;
        float* Wd = Wsm + st * 4352;
#pragma unroll
        for (int i = 0; i < 4; i++) {
            int f4 = tid + i * 256;
            int m = f4 >> 3, kc = f4 & 7;
            cpasync16(&Ad[m * 36 + kc * 4], &A[(size_t)(m0 + m) * lda + k0 + kc * 4]);
        }
#pragma unroll
        for (int i = 0; i < 4; i++) {
            int f4 = tid + i * 256;
            int k = f4 >> 5, nc = f4 & 31;
            cpasync16(&Wd[k * 136 + nc * 4], &W[(size_t)(k0 + k) * N + n0 + nc * 4]);
        }
    };

    auto compute = [&](int st) {
        const float* As = Asm + st * 4608;
        const float* Ws = Wsm + st * 4352;
#pragma unroll
        for (int kk = 0; kk < 4; kk++) {
            unsigned bf[4][2];
#pragma unroll
            for (int nt = 0; nt < 4; nt++) {
                bf[nt][0] = __float_as_uint(Ws[(kk * 8 + tig) * 136 + wn + nt * 8 + gid]);
                bf[nt][1] = __float_as_uint(Ws[(kk * 8 + 4 + tig) * 136 + wn + nt * 8 + gid]);
            }
#pragma unroll
            for (int mt = 0; mt < 4; mt++) {
                int r0 = (wm + mt * 16 + gid) * 36;
                int r1 = (wm + mt * 16 + 8 + gid) * 36;
                unsigned a0 = __float_as_uint(As[r0 + kk * 8 + tig]);
                unsigned a1 = __float_as_uint(As[r1 + kk * 8 + tig]);
                unsigned a2 = __float_as_uint(As[r0 + kk * 8 + 4 + tig]);
                unsigned a3 = __float_as_uint(As[r1 + kk * 8 + 4 + tig]);
#pragma unroll
                for (int nt = 0; nt < 4; nt++)
                    mma_tf32(acc[mt][nt], a0, a1, a2, a3, bf[nt][0], bf[nt][1]);
            }
        }
    };

    const int nch = K >> 5;
    load_chunk(0, 0);
    asm volatile("cp.async.commit_group;\n");
    load_chunk(1, 32);
    asm volatile("cp.async.commit_group;\n");
    for (int ch = 0; ch < nch; ch++) {
        if (ch + 2 < nch) {
            load_chunk((ch + 2) % 3, (ch + 2) * 32);
            asm volatile("cp.async.commit_group;\n");
            asm volatile("cp.async.wait_group 2;\n");
        } else if (ch + 1 < nch) {
            asm volatile("cp.async.wait_group 1;\n");
        } else {
            asm volatile("cp.async.wait_group 0;\n");
        }
        __syncthreads();
        compute(ch % 3);
        __syncthreads();
    }

#pragma unroll
    for (int nt = 0; nt < 4; nt++) {
        int col = n0 + wn + nt * 8 + 2 * tig;
        float b0v = bias[col], b1v = bias[col + 1];
#pragma unroll
        for (int mt = 0; mt < 4; mt++) {
            int row0 = m0 + wm + mt * 16 + gid;
            int row1 = row0 + 8;
            int o0 = remap ? ((row0 & (BB - 1)) * TT + (row0 >> 7)) : row0;
            int o1 = remap ? ((row1 & (BB - 1)) * TT + (row1 >> 7)) : row1;
            float2 v0, v1;
            v0.x = acc[mt][nt][0] + b0v; v0.y = acc[mt][nt][1] + b1v;
            v1.x = acc[mt][nt][2] + b0v; v1.y = acc[mt][nt][3] + b1v;
            *reinterpret_cast<float2*>(&C[(size_t)o0 * N + col]) = v0;
            *reinterpret_cast<float2*>(&C[(size_t)o1 * N + col]) = v1;
        }
    }
}

// ---------------- bridge ----------------------------------------------------
__global__ void bridge_kernel(const float* __restrict__ hW, const float* __restrict__ hb,
                              const float* __restrict__ cW, const float* __restrict__ cb)
{
    int p = blockIdx.x * blockDim.x + threadIdx.x;
    int j = p & (HH - 1);
    int b = p >> 9;
    float sh = hb[j], sc = cb[j];
    const float* hrow = g_fin[0] + (size_t)b * 2 * HH;
    const float* crow = g_fin[1] + (size_t)b * 2 * HH;
    for (int k = 0; k < 2 * HH; k++) {
        sh += hrow[k] * hW[(size_t)k * HH + j];
        sc += crow[k] * cW[(size_t)k * HH + j];
    }
    g_hinit[(size_t)b * HH + j] = tanhf(sh);
    g_cinit[(size_t)b * HH + j] = tanhf(sc);
}

// ---------------- bf16 MMA recurrence (unchanged numerics from R13) ----------
__device__ __forceinline__ void mma_bf16(float* c, const unsigned* a,
                                         unsigned b0, unsigned b1) {
    asm volatile(
        "mma.sync.aligned.m16n8k16.row.col.f32.bf16.bf16.f32 "
        "{%0,%1,%2,%3}, {%4,%5,%6,%7}, {%8,%9}, {%0,%1,%2,%3};"
        : "+f"(c[0]), "+f"(c[1]), "+f"(c[2]), "+f"(c[3])
        : "r"(a[0]), "r"(a[1]), "r"(a[2]), "r"(a[3]), "r"(b0), "r"(b1));
}

__device__ __forceinline__ float sigm_(float v) { return 1.f / (1.f + expf(-v)); }

struct RCell2 {
    const float* pre;
    const unsigned* whi; const unsigned* wlo;
    float* hs; int ldh; int colofs;
    const float* cinit;
    unsigned* h0hi; unsigned* h0lo;
    unsigned* h1hi; unsigned* h1lo;
    float* finH; float* finC; int finOfs;
    int rev;
};

template <int MT>
__global__ __launch_bounds__(256) void recur2_kernel(
    RCell2 c0, RCell2 c1, int nbpc, unsigned nb, unsigned* barC)
{
    extern __shared__ unsigned smu[];
    unsigned* Wphi = smu;
    unsigned* Wplo = smu + 18432;
    unsigned* Aphi = smu + 36864;
    unsigned* Aplo = smu + 41472;
    float* ex = (float*)(smu + 46080);

    const int tid = threadIdx.x;
    const bool c1sel = (blockIdx.x >= nbpc);
    const RCell2 C = c1sel ? c1 : c0;
    const int bic = c1sel ? (blockIdx.x - nbpc) : blockIdx.x;
    const int bn = bic & 31;
    const int m0 = (bic >> 5) * MT;
    const int j0 = bn * 16;
    const int warp = tid >> 5, lane = tid & 31;
    const int gid = lane >> 2, tig = lane & 3;
    const int wm = warp & 1, wn = warp >> 1;
    constexpr int WTM = MT / 32;

    {
        const uint4* srch = reinterpret_cast<const uint4*>(C.whi + (size_t)bn * 16384);
        const uint4* srcl = reinterpret_cast<const uint4*>(C.wlo + (size_t)bn * 16384);
#pragma unroll
        for (int i = 0; i < 16; i++) {
            int f4 = tid + i * 256;
            int row = f4 >> 4, q = f4 & 15;
            *reinterpret_cast<uint4*>(&Wphi[row * 72 + q * 4]) = srch[f4];
            *reinterpret_cast<uint4*>(&Wplo[row * 72 + q * 4]) = srcl[f4];
        }
    }

    const int pm = tid & (MT - 1);
    const int pjq = tid / MT;
    const bool pact = pjq < 4;
    float creg[4] = {0.f, 0.f, 0.f, 0.f};
    if (pact && C.cinit) {
        float4 cv = __ldcg(reinterpret_cast<const float4*>(
            &C.cinit[(size_t)(m0 + pm) * HH + j0 + pjq * 4]));
        creg[0] = cv.x; creg[1] = cv.y; creg[2] = cv.z; creg[3] = cv.w;
    }
    __syncthreads();

    for (int s = 0; s < TT; s++) {
        const int t = C.rev ? (TT - 1 - s) : s;
        const unsigned* rhi = (s & 1) ? C.h1hi : C.h0hi;
        const unsigned* rlo = (s & 1) ? C.h1lo : C.h0lo;
        unsigned* whi_ = (s & 1) ? C.h0hi : C.h1hi;
        unsigned* wlo_ = (s & 1) ? C.h0lo : C.h1lo;
        const float* preb = C.pre + (size_t)t * BB * G4;

        float4 pg[4];
        if (pact) {
#pragma unroll
            for (int g = 0; g < 4; g++)
                pg[g] = __ldg(reinterpret_cast<const float4*>(
                    &preb[(size_t)(m0 + pm) * G4 + g * HH + j0 + pjq * 4]));
        }

        float acc[WTM][2][4];
#pragma unroll
        for (int mt = 0; mt < WTM; mt++)
#pragma unroll
            for (int nt = 0; nt < 2; nt++)
#pragma unroll
                for (int u = 0; u < 4; u++) acc[mt][nt][u] = 0.f;

        for (int ch = 0; ch < 4; ch++) {
            __syncthreads();
            {
                constexpr int F4 = 64 * MT / 4;
                constexpr int PT = F4 / 256;
                const int kpb = ch * 64;
#pragma unroll
                for (int i = 0; i < PT; i++) {
                    int f4 = tid + i * 256;
                    int row = f4 / (MT / 4), q = f4 % (MT / 4);
                    *reinterpret_cast<uint4*>(&Aphi[row * 72 + q * 4]) =
                        __ldcg(reinterpret_cast<const uint4*>(
                            &rhi[(size_t)(kpb + row) * 128 + m0 + q * 4]));
                    *reinterpret_cast<uint4*>(&Aplo[row * 72 + q * 4]) =
                        __ldcg(reinterpret_cast<const uint4*>(
                            &rlo[(size_t)(kpb + row) * 128 + m0 + q * 4]));
                }
            }
            __syncthreads();
#pragma unroll
            for (int kc = 0; kc < 8; kc++) {
                const int r0 = (kc * 8 + tig) * 72;
                const int r1 = r0 + 4 * 72;
                unsigned ah[WTM][4], al[WTM][4];
#pragma unroll
                for (int mt = 0; mt < WTM; mt++) {
                    const int am = wm * (MT / 2) + mt * 16 + gid;
                    ah[mt][0] = Aphi[r0 + am]; ah[mt][1] = Aphi[r0 + am + 8];
                    ah[mt][2] = Aphi[r1 + am]; ah[mt][3] = Aphi[r1 + am + 8];
                    al[mt][0] = Aplo[r0 + am]; al[mt][1] = Aplo[r0 + am + 8];
                    al[mt][2] = Aplo[r1 + am]; al[mt][3] = Aplo[r1 + am + 8];
                }
                const int wr0 = (ch * 64 + kc * 8 + tig) * 72;
                const int wr1 = wr0 + 4 * 72;
#pragma unroll
                for (int nt = 0; nt < 2; nt++) {
                    const int nn = wn * 16 + nt * 8 + gid;
                    unsigned bh0 = Wphi[wr0 + nn], bh1 = Wphi[wr1 + nn];
                    unsigned bl0 = Wplo[wr0 + nn], bl1 = Wplo[wr1 + nn];
#pragma unroll
                    for (int mt = 0; mt < WTM; mt++) {
                        mma_bf16(acc[mt][nt], ah[mt], bh0, bh1);
                        mma_bf16(acc[mt][nt], ah[mt], bl0, bl1);
                        mma_bf16(acc[mt][nt], al[mt], bh0, bh1);
                    }
                }
            }
        }

#pragma unroll
        for (int mt = 0; mt < WTM; mt++)
#pragma unroll
            for (int nt = 0; nt < 2; nt++) {
                int mr = (wm * (MT / 2) + mt * 16 + gid) * 72;
                int col = wn * 16 + nt * 8 + 2 * tig;
                float2 v0, v1;
                v0.x = acc[mt][nt][0]; v0.y = acc[mt][nt][1];
                v1.x = acc[mt][nt][2]; v1.y = acc[mt][nt][3];
                *reinterpret_cast<float2*>(&ex[mr + col]) = v0;
                *reinterpret_cast<float2*>(&ex[mr + 8 * 72 + col]) = v1;
            }
        __syncthreads();

        if (pact) {
            float4 gi = *reinterpret_cast<const float4*>(&ex[pm * 72 + 0  + pjq * 4]);
            float4 gf = *reinterpret_cast<const float4*>(&ex[pm * 72 + 16 + pjq * 4]);
            float4 gg = *reinterpret_cast<const float4*>(&ex[pm * 72 + 32 + pjq * 4]);
            float4 go = *reinterpret_cast<const float4*>(&ex[pm * 72 + 48 + pjq * 4]);
            float I[4] = {gi.x + pg[0].x, gi.y + pg[0].y, gi.z + pg[0].z, gi.w + pg[0].w};
            float F[4] = {gf.x + pg[1].x, gf.y + pg[1].y, gf.z + pg[1].z, gf.w + pg[1].w};
            float Gg[4] = {gg.x + pg[2].x, gg.y + pg[2].y, gg.z + pg[2].z, gg.w + pg[2].w};
            float O[4] = {go.x + pg[3].x, go.y + pg[3].y, go.z + pg[3].z, go.w + pg[3].w};
            float hn[4];
#pragma unroll
            for (int u = 0; u < 4; u++) {
                float cn = sigm_(F[u]) * creg[u] + sigm_(I[u]) * tanhf(Gg[u]);
                hn[u] = sigm_(O[u]) * tanhf(cn);
                creg[u] = cn;
            }
            __nv_bfloat16 b0 = __float2bfloat16_rn(hn[0]);
            __nv_bfloat16 b1 = __float2bfloat16_rn(hn[1]);
            __nv_bfloat16 b2 = __float2bfloat16_rn(hn[2]);
            __nv_bfloat16 b3 = __float2bfloat16_rn(hn[3]);
            unsigned hp0 = (unsigned)__bfloat16_as_ushort(b0) |
                           ((unsigned)__bfloat16_as_ushort(b1) << 16);
            unsigned hp1 = (unsigned)__bfloat16_as_ushort(b2) |
                           ((unsigned)__bfloat16_as_ushort(b3) << 16);
            unsigned lp0 = pack_bf16x2(hn[0] - __bfloat162float(b0),
                                       hn[1] - __bfloat162float(b1));
            unsigned lp1 = pack_bf16x2(hn[2] - __bfloat162float(b2),
                                       hn[3] - __bfloat162float(b3));
            int kp0 = (j0 + pjq * 4) >> 1;
            __stcg(&whi_[(size_t)kp0 * 128 + m0 + pm], hp0);
            __stcg(&whi_[(size_t)(kp0 + 1) * 128 + m0 + pm], hp1);
            __stcg(&wlo_[(size_t)kp0 * 128 + m0 + pm], lp0);
            __stcg(&wlo_[(size_t)(kp0 + 1) * 128 + m0 + pm], lp1);
            if (C.hs) {
                float4 hv;
                hv.x = tfr(hn[0]); hv.y = tfr(hn[1]);
                hv.z = tfr(hn[2]); hv.w = tfr(hn[3]);
                *reinterpret_cast<float4*>(
                    &C.hs[(size_t)t * BB * C.ldh + (size_t)(m0 + pm) * C.ldh +
                          C.colofs + j0 + pjq * 4]) = hv;
            }
            if (s == TT - 1 && C.finH) {
                float4 hv; hv.x = hn[0]; hv.y = hn[1]; hv.z = hn[2]; hv.w = hn[3];
                float4 cv; cv.x = creg[0]; cv.y = creg[1]; cv.z = creg[2]; cv.w = creg[3];
                *reinterpret_cast<float4*>(
                    &C.finH[(size_t)(m0 + pm) * 2 * HH + C.finOfs + j0 + pjq * 4]) = hv;
                *reinterpret_cast<float4*>(
                    &C.finC[(size_t)(m0 + pm) * 2 * HH + C.finOfs + j0 + pjq * 4]) = cv;
            }
        }

        __threadfence();
        __syncthreads();
        if (tid == 0) {
            atomicAdd(barC, 1u);
            unsigned target = (unsigned)(s + 1) * nb;
            while (*((volatile unsigned*)barC) < target) __nanosleep(64);
            __threadfence();
        }
        __syncthreads();
    }
}

// ---------------- host ------------------------------------------------------
static void* symaddr_(const void* sym) {
    void* p = nullptr;
    cudaGetSymbolAddress(&p, sym);
    return p;
}

extern "C" void kernel_launch(void* const* d_in, const int* in_sizes, int n_in,
                              void* d_out, int out_size)
{
    const int*   x       = (const int*)  d_in[0];
    const float* emb     = (const float*)d_in[1];
    const float* efWx0   = (const float*)d_in[2];
    const float* efWh0   = (const float*)d_in[3];
    const float* efb0    = (const float*)d_in[4];
    const float* efWx1   = (const float*)d_in[5];
    const float* efWh1   = (const float*)d_in[6];
    const float* efb1    = (const float*)d_in[7];
    const float* ebWx0   = (const float*)d_in[8];
    const float* ebWh0   = (const float*)d_in[9];
    const float* ebb0    = (const float*)d_in[10];
    const float* ebWx1   = (const float*)d_in[11];
    const float* ebWh1   = (const float*)d_in[12];
    const float* ebb1    = (const float*)d_in[13];
    const float* dWx0    = (const float*)d_in[14];
    const float* dWh0    = (const float*)d_in[15];
    const float* db0     = (const float*)d_in[16];
    const float* dWx1    = (const float*)d_in[17];
    const float* dWh1    = (const float*)d_in[18];
    const float* db1     = (const float*)d_in[19];
    const float* hprojW  = (const float*)d_in[20];
    const float* hprojb  = (const float*)d_in[21];
    const float* cprojW  = (const float*)d_in[22];
    const float* cprojb  = (const float*)d_in[23];
    const float* fcW     = (const float*)d_in[24];
    const float* fcb     = (const float*)d_in[25];

    float* pX    = (float*)symaddr_(g_X);
    float* pPre0 = (float*)symaddr_(g_pre0);
    float* pPre1 = (float*)symaddr_(g_pre1);
    float* pCat  = (float*)symaddr_(g_cat);
    float* pHs0  = (float*)symaddr_(g_hs0);
    float* pHs1  = (float*)symaddr_(g_hs1);
    float* pFin  = (float*)symaddr_(g_fin);
    float* pHin  = (float*)symaddr_(g_hinit);
    float* pCin  = (float*)symaddr_(g_cinit);
    unsigned* pBar = (unsigned*)symaddr_(g_barC);
    unsigned* pWsp = (unsigned*)symaddr_(g_wsp);
    unsigned* pHsp = (unsigned*)symaddr_(g_hsp);
    float* pWx   = (float*)symaddr_(g_wx);

    const int M = TT * BB;
    const int SME2 = 50688 * 4;
    const int SMEG = 26880 * 4;   // 107520 B, 3 stages
    cudaFuncSetAttribute(recur2_kernel<64>, cudaFuncAttributeMaxDynamicSharedMemorySize, SME2);
    cudaFuncSetAttribute(recur2_kernel<32>, cudaFuncAttributeMaxDynamicSharedMemorySize, SME2);
    cudaFuncSetAttribute(tgemm_kernel, cudaFuncAttributeMaxDynamicSharedMemorySize, SMEG);

    const size_t WSZ = 32 * 256 * 64;
    auto wsp = [&](int w, int hl) { return pWsp + ((size_t)w * 2 + hl) * WSZ; };
    auto hsp = [&](int cell, int buf, int hl) {
        return pHsp + (((size_t)cell * 2 + buf) * 2 + hl) * 32768;
    };
    auto wx = [&](int i) { return pWx + (size_t)i * 2097152; };

    dim3 gpre2(G4 / 128, M / 128, 2);
    dim3 gpre1(G4 / 128, M / 128, 1);
    dim3 gfc(VV / 128, M / 128, 1);

    // --- launches 1-6: positioned so #6 = enc L0 recurrence (ncu -s 5 -c 1) ---
    // 1. embedding (tf32 at write)
    embed_kernel<<<TT * BB * (EE / 4) / 256, 256>>>(x, emb);
    // 2. tf32-round enc L0 input weights (paired)
    tfround2_kernel<<<dim3(2048, 1, 2), 256>>>(efWx0, wx(0), EE * G4, ebWx0, wx(1), EE * G4);
    // 3. split enc L0 recurrent weights (paired)
    wconv2_kernel<<<dim3(2048, 1, 2), 256>>>(efWh0, wsp(0, 0), wsp(0, 1),
                                             ebWh0, wsp(1, 0), wsp(1, 1));
    // 4. enc L0 precompute, fwd+bwd in one launch (K=256)
    tgemm_kernel<<<gpre2, 256, SMEG>>>(pX, wx(0), efb0, pPre0,
                                       pX, wx(1), ebb0, pPre1, M, G4, EE, EE, 0);
    // 5. zero h buffers + barrier
    initzero_kernel<<<1024, 256>>>((float*)pHsp, pBar);
    // 6. enc L0 recurrence  <-- PROFILED LAUNCH
    {
        RCell2 cf{pPre0, wsp(0, 0), wsp(0, 1), pCat, 2 * HH, 0, nullptr,
                  hsp(0, 0, 0), hsp(0, 0, 1), hsp(0, 1, 0), hsp(0, 1, 1),
                  nullptr, nullptr, 0, 0};
        RCell2 cb{pPre1, wsp(1, 0), wsp(1, 1), pCat, 2 * HH, HH, nullptr,
                  hsp(1, 0, 0), hsp(1, 0, 1), hsp(1, 1, 0), hsp(1, 1, 1),
                  nullptr, nullptr, 0, 1};
        recur2_kernel<64><<<128, 256, SME2>>>(cf, cb, 64, 128u, pBar);
    }

    // 7-8. enc L1 weight prep
    tfround2_kernel<<<dim3(8192, 1, 2), 256>>>(efWx1, wx(2), 2 * HH * G4,
                                               ebWx1, wx(3), 2 * HH * G4);
    wconv2_kernel<<<dim3(2048, 1, 2), 256>>>(efWh1, wsp(2, 0), wsp(2, 1),
                                             ebWh1, wsp(3, 0), wsp(3, 1));
    // 9. enc L1 precompute (K=1024)
    tgemm_kernel<<<gpre2, 256, SMEG>>>(pCat, wx(2), efb1, pPre0,
                                       pCat, wx(3), ebb1, pPre1, M, G4, 2 * HH, 2 * HH, 0);
    // 10-11. enc L1 recurrence (finals only)
    initzero_kernel<<<1024, 256>>>((float*)pHsp, pBar);
    {
        RCell2 ef{pPre0, wsp(2, 0), wsp(2, 1), nullptr, 0, 0, nullptr,
                  hsp(0, 0, 0), hsp(0, 0, 1), hsp(0, 1, 0), hsp(0, 1, 1),
                  pFin, pFin + (size_t)BB * 2 * HH, 0, 0};
        RCell2 eb{pPre1, wsp(3, 0), wsp(3, 1), nullptr, 0, 0, nullptr,
                  hsp(1, 0, 0), hsp(1, 0, 1), hsp(1, 1, 0), hsp(1, 1, 1),
                  pFin, pFin + (size_t)BB * 2 * HH, HH, 1};
        recur2_kernel<64><<<128, 256, SME2>>>(ef, eb, 64, 128u, pBar);
    }

    // 12. bridge
    bridge_kernel<<<(BB * HH) / 256, 256>>>(hprojW, hprojb, cprojW, cprojb);

    // 13-14. decoder weight prep
    tfround2_kernel<<<dim3(4096, 1, 2), 256>>>(dWx0, wx(4), EE * G4,
                                               dWx1, wx(5), HH * G4);
    wconv2_kernel<<<dim3(2048, 1, 2), 256>>>(dWh0, wsp(4, 0), wsp(4, 1),
                                             dWh1, wsp(5, 0), wsp(5, 1));
    // 15. dec L0 precompute (K=256)
    tgemm_kernel<<<gpre1, 256, SMEG>>>(pX, wx(4), db0, pPre0,
                                       pX, wx(4), db0, pPre0, M, G4, EE, EE, 0);
    // 16-18. dec L0 recurrence
    initbar_kernel<<<1, 1>>>(pBar);
    hsplit_kernel<<<128, 256>>>(pHin, hsp(0, 0, 0), hsp(0, 0, 1));
    {
        RCell2 d0{pPre0, wsp(4, 0), wsp(4, 1), pHs0, HH, 0, pCin,
                  hsp(0, 0, 0), hsp(0, 0, 1), hsp(0, 1, 0), hsp(0, 1, 1),
                  nullptr, nullptr, 0, 0};
        recur2_kernel<32><<<128, 256, SME2>>>(d0, d0, 128, 128u, pBar);
    }

    // 19. round FC weights
    tfround_kernel<<<1024, 256>>>(fcW, wx(6), HH * VV);
    // 20. dec L1 precompute (K=512)
    tgemm_kernel<<<gpre1, 256, SMEG>>>(pHs0, wx(5), db1, pPre1,
                                       pHs0, wx(5), db1, pPre1, M, G4, HH, HH, 0);
    // 21-23. dec L1 recurrence
    initbar_kernel<<<1, 1>>>(pBar);
    hsplit_kernel<<<128, 256>>>(pHin, hsp(0, 0, 0), hsp(0, 0, 1));
    {
        RCell2 d1{pPre1, wsp(5, 0), wsp(5, 1), pHs1, HH, 0, pCin,
                  hsp(0, 0, 0), hsp(0, 0, 1), hsp(0, 1, 0), hsp(0, 1, 1),
                  nullptr, nullptr, 0, 0};
        recur2_kernel<32><<<128, 256, SME2>>>(d1, d1, 128, 128u, pBar);
    }

    // 24. final FC with remap
    tgemm_kernel<<<gfc, 256, SMEG>>>(pHs1, wx(6), fcb, (float*)d_out,
                                     pHs1, wx(6), fcb, (float*)d_out, M, VV, HH, HH, 1);
}